// round 5
// baseline (speedup 1.0000x reference)
#include <cuda_runtime.h>
#include <math.h>

// ---------------- problem constants ----------------
#define NVOX   60000
#define DIM    128
#define NLAYER 12
#define NYY    400
#define NXX    400
#define NPIX   (2*NYY*NXX)

#define LN0  24000
#define LN1  36000
#define CAP0 25
#define CAP1 100
#define NW0  960
#define NW1  360

#define TILEW    36                 // padded smem row width (words); 144B rows keep 16B cp.async alignment
#define TILE_ELE (128*TILEW)
#define SMEMB    (2*3*TILE_ELE*4)   // 3-stage double operand: 110592 B

// ---------------- static scratch ----------------
__device__ float g_pos   [2][NVOX*DIM];
__device__ float g_feat  [NVOX*DIM];
__device__ float g_resid [NVOX*DIM];
__device__ float g_qkin  [LN1*DIM];
__device__ float g_qk    [LN1*2*DIM];
__device__ float g_v     [LN1*DIM];
__device__ float g_ao    [LN1*DIM];
__device__ float g_h     [NVOX*256];
__device__ float g_canvas[(size_t)NPIX*DIM];
__device__ float g_bev   [(size_t)NPIX*DIM];
__device__ float g_wt    [2*DIM*9*DIM];

// ---------------- helpers ----------------
__device__ __forceinline__ unsigned f2tf(float x) {
    unsigned u;
    asm("cvt.rna.tf32.f32 %0, %1;" : "=r"(u) : "f"(x));
    return u;
}
__device__ __forceinline__ void mma8(float* d, const unsigned* a, const unsigned* b) {
    asm volatile(
        "mma.sync.aligned.m16n8k8.row.col.f32.tf32.tf32.f32 "
        "{%0,%1,%2,%3}, {%4,%5,%6,%7}, {%8,%9}, {%0,%1,%2,%3};"
        : "+f"(d[0]), "+f"(d[1]), "+f"(d[2]), "+f"(d[3])
        : "r"(a[0]), "r"(a[1]), "r"(a[2]), "r"(a[3]), "r"(b[0]), "r"(b[1]));
}
__device__ __forceinline__ void cpa16(float* sptr, const float* gptr, int srcsize) {
    unsigned sa = (unsigned)__cvta_generic_to_shared(sptr);
    asm volatile("cp.async.cg.shared.global [%0], [%1], 16, %2;"
                 :: "r"(sa), "l"(gptr), "r"(srcsize) : "memory");
}
#define CP_COMMIT() asm volatile("cp.async.commit_group;" ::: "memory")
#define CP_WAIT1()  asm volatile("cp.async.wait_group 1;" ::: "memory")
#define CP_WAIT0()  asm volatile("cp.async.wait_group 0;" ::: "memory")

// ---------------- positional embedding ----------------
__global__ void pos_kernel(const float* __restrict__ ciw0, const float* __restrict__ ciw1,
                           float* __restrict__ pos)
{
    int n = blockIdx.x, s = blockIdx.y, c = threadIdx.x;
    const float* ciw = s ? ciw1 : ciw0;
    int axis = c >> 6, j2 = c & 63, j = j2 >> 1;
    float freq = powf(10000.0f, (float)j * (1.0f/32.0f));
    float v = (ciw[n*2 + axis] - 6.0f) / freq;
    pos[(size_t)s*NVOX*DIM + (size_t)n*DIM + c] = (j2 & 1) ? cosf(v) : sinf(v);
}

// ---------------- gather for QK input (feat + pos, level-compact) ----------------
__global__ void gatherQ_kernel(const float* __restrict__ feat, const float* __restrict__ pos,
                               const int* __restrict__ vx, float* __restrict__ qkin)
{
    int j = blockIdx.x, c = threadIdx.x;
    int vv = vx[j];
    qkin[(size_t)j*DIM + c] = feat[(size_t)vv*DIM + c] + pos[(size_t)vv*DIM + c];
}

// ---------------- TF32 tensor-core GEMM, cp.async 3-stage pipeline ----------------
// C[M,N] = A'[M,K] @ W[N,K]^T + bias
// AMODE: 0 = A direct; 2 = A rows gathered via vx (K must be 128)
// OMODE: 0 = direct store to C; 1 = scatter: C[vx[row]] = res[vx[row]] + val  (N must be 128)
// EPI:   1 = exact GELU
template<int EPI, int AMODE, int OMODE>
__global__ void __launch_bounds__(256, 1)
gemm_tc(const float* __restrict__ A, const float* __restrict__ W,
        const float* __restrict__ bias, float* __restrict__ C,
        const int* __restrict__ vx, const float* __restrict__ res,
        int M, int N, int K)
{
    extern __shared__ float sm[];
    float* As = sm;
    float* Ws = sm + 3*TILE_ELE;
    int tid = threadIdx.x, lane = tid & 31, warp = tid >> 5;
    int g = lane >> 2, tig = lane & 3;
    int wm = warp & 3, wn = warp >> 2;
    int bm = blockIdx.y * 128, bn = blockIdx.x * 128;

    const float* aRow[4];
    int okA[4], rW[4], cc8[4];
    #pragma unroll
    for (int l = 0; l < 4; l++) {
        int f = tid + l*256;
        rW[l] = f >> 3; cc8[l] = (f & 7) << 2;
        int row = bm + rW[l];
        okA[l] = (row < M) ? 16 : 0;
        int src = (row < M) ? (AMODE ? vx[row] : row) : 0;
        aRow[l] = A + (size_t)src * K;
    }
    int NT = K >> 5;

    auto issue = [&](int t, int buf) {
        float* Ab = As + buf*TILE_ELE;
        float* Wb = Ws + buf*TILE_ELE;
        int k0 = t << 5;
        #pragma unroll
        for (int l = 0; l < 4; l++) {
            cpa16(Ab + rW[l]*TILEW + cc8[l], aRow[l] + k0 + cc8[l], okA[l]);
            cpa16(Wb + rW[l]*TILEW + cc8[l], W + (size_t)(bn + rW[l])*K + k0 + cc8[l], 16);
        }
        CP_COMMIT();
    };

    float acc[2][8][4];
    #pragma unroll
    for (int i = 0; i < 2; i++)
        #pragma unroll
        for (int j = 0; j < 8; j++)
            #pragma unroll
            for (int q = 0; q < 4; q++) acc[i][j][q] = 0.0f;

    issue(0, 0); issue(1, 1);
    for (int it = 0; it < NT; it++) {
        if (it < NT-1) CP_WAIT1(); else CP_WAIT0();
        __syncthreads();
        if (it + 2 < NT) issue(it + 2, (it + 2) % 3);
        const float* Ab = As + (it % 3)*TILE_ELE;
        const float* Wb = Ws + (it % 3)*TILE_ELE;
        #pragma unroll
        for (int kk = 0; kk < 4; kk++) {
            unsigned a[2][4], b[8][2];
            #pragma unroll
            for (int tm = 0; tm < 2; tm++) {
                int rr = wm*32 + tm*16 + g;
                a[tm][0] = f2tf(Ab[rr*TILEW + kk*8 + tig]);
                a[tm][1] = f2tf(Ab[(rr+8)*TILEW + kk*8 + tig]);
                a[tm][2] = f2tf(Ab[rr*TILEW + kk*8 + tig + 4]);
                a[tm][3] = f2tf(Ab[(rr+8)*TILEW + kk*8 + tig + 4]);
            }
            #pragma unroll
            for (int tn = 0; tn < 8; tn++) {
                int cc = wn*64 + tn*8 + g;
                b[tn][0] = f2tf(Wb[cc*TILEW + kk*8 + tig]);
                b[tn][1] = f2tf(Wb[cc*TILEW + kk*8 + tig + 4]);
            }
            #pragma unroll
            for (int tm = 0; tm < 2; tm++)
                #pragma unroll
                for (int tn = 0; tn < 8; tn++)
                    mma8(acc[tm][tn], a[tm], b[tn]);
        }
    }

    #pragma unroll
    for (int tm = 0; tm < 2; tm++) {
        int row0 = bm + wm*32 + tm*16 + g;
        #pragma unroll
        for (int tn = 0; tn < 8; tn++) {
            int col = bn + wn*64 + tn*8 + 2*tig;
            float b0 = bias[col], b1 = bias[col+1];
            #pragma unroll
            for (int h = 0; h < 2; h++) {
                int row = row0 + h*8;
                if (row >= M) continue;
                float v0 = acc[tm][tn][2*h+0] + b0;
                float v1 = acc[tm][tn][2*h+1] + b1;
                if (EPI == 1) {
                    v0 = 0.5f * v0 * (1.0f + erff(v0 * 0.70710678118654752f));
                    v1 = 0.5f * v1 * (1.0f + erff(v1 * 0.70710678118654752f));
                }
                if (OMODE == 1) {
                    int vv = vx[row];
                    float2 rv = *(const float2*)(res + (size_t)vv*128 + col);
                    *(float2*)(C + (size_t)vv*128 + col) = make_float2(rv.x + v0, rv.y + v1);
                } else {
                    *(float2*)(C + (size_t)row*N + col) = make_float2(v0, v1);
                }
            }
        }
    }
}

// ---------------- TF32 implicit-GEMM dilated conv + BN(eval) + ReLU, cp.async pipeline ----------------
__global__ void __launch_bounds__(256, 1)
conv_tc(const float* __restrict__ in, const float* __restrict__ wt,
        const float* __restrict__ bg, const float* __restrict__ bb,
        const float* __restrict__ bm_, const float* __restrict__ bv,
        float* __restrict__ out)
{
    extern __shared__ float sm[];
    float* As = sm;
    float* Ws = sm + 3*TILE_ELE;
    int tid = threadIdx.x, lane = tid & 31, warp = tid >> 5;
    int g = lane >> 2, tig = lane & 3;
    int wm = warp & 3, wn = warp >> 2;
    int pm0 = blockIdx.x * 128;

    int rW[4], cc8[4], pb[4], py[4], px[4];
    #pragma unroll
    for (int l = 0; l < 4; l++) {
        int f = tid + l*256;
        rW[l] = f >> 3; cc8[l] = (f & 7) << 2;
        int p = pm0 + rW[l];
        pb[l] = p / (NYY*NXX);
        int rem = p - pb[l]*(NYY*NXX);
        py[l] = rem / NXX; px[l] = rem % NXX;
    }

    auto issue = [&](int t, int buf) {
        float* Ab = As + buf*TILE_ELE;
        float* Wb = Ws + buf*TILE_ELE;
        int tap = t >> 2, kc = (t & 3) << 5;
        int dy = (tap/3)*2 - 2, dx = (tap%3)*2 - 2;
        #pragma unroll
        for (int l = 0; l < 4; l++) {
            int yy = py[l] + dy, xx = px[l] + dx;
            int ok = ((unsigned)yy < NYY && (unsigned)xx < NXX) ? 16 : 0;
            int yc = ok ? yy : 0, xc = ok ? xx : 0;
            const float* src = in + ((size_t)((pb[l]*NYY + yc)*NXX + xc))*DIM + kc + cc8[l];
            cpa16(Ab + rW[l]*TILEW + cc8[l], src, ok);
            cpa16(Wb + rW[l]*TILEW + cc8[l], wt + (size_t)rW[l]*1152 + tap*128 + kc + cc8[l], 16);
        }
        CP_COMMIT();
    };

    float acc[2][8][4];
    #pragma unroll
    for (int i = 0; i < 2; i++)
        #pragma unroll
        for (int j = 0; j < 8; j++)
            #pragma unroll
            for (int q = 0; q < 4; q++) acc[i][j][q] = 0.0f;

    const int NT = 36;
    issue(0, 0); issue(1, 1);
    for (int it = 0; it < NT; it++) {
        if (it < NT-1) CP_WAIT1(); else CP_WAIT0();
        __syncthreads();
        if (it + 2 < NT) issue(it + 2, (it + 2) % 3);
        const float* Ab = As + (it % 3)*TILE_ELE;
        const float* Wb = Ws + (it % 3)*TILE_ELE;
        #pragma unroll
        for (int kk = 0; kk < 4; kk++) {
            unsigned a[2][4], b[8][2];
            #pragma unroll
            for (int tm = 0; tm < 2; tm++) {
                int rr = wm*32 + tm*16 + g;
                a[tm][0] = f2tf(Ab[rr*TILEW + kk*8 + tig]);
                a[tm][1] = f2tf(Ab[(rr+8)*TILEW + kk*8 + tig]);
                a[tm][2] = f2tf(Ab[rr*TILEW + kk*8 + tig + 4]);
                a[tm][3] = f2tf(Ab[(rr+8)*TILEW + kk*8 + tig + 4]);
            }
            #pragma unroll
            for (int tn = 0; tn < 8; tn++) {
                int cc = wn*64 + tn*8 + g;
                b[tn][0] = f2tf(Wb[cc*TILEW + kk*8 + tig]);
                b[tn][1] = f2tf(Wb[cc*TILEW + kk*8 + tig + 4]);
            }
            #pragma unroll
            for (int tm = 0; tm < 2; tm++)
                #pragma unroll
                for (int tn = 0; tn < 8; tn++)
                    mma8(acc[tm][tn], a[tm], b[tn]);
        }
    }

    #pragma unroll
    for (int tm = 0; tm < 2; tm++) {
        int row0 = pm0 + wm*32 + tm*16 + g;
        #pragma unroll
        for (int tn = 0; tn < 8; tn++) {
            int oc = wn*64 + tn*8 + 2*tig;
            float s0 = bg[oc]   * rsqrtf(bv[oc]   + 1e-3f);
            float s1 = bg[oc+1] * rsqrtf(bv[oc+1] + 1e-3f);
            float h0 = bb[oc]   - bm_[oc]  *s0;
            float h1 = bb[oc+1] - bm_[oc+1]*s1;
            #pragma unroll
            for (int h = 0; h < 2; h++) {
                int row = row0 + h*8;
                float v0 = fmaxf(acc[tm][tn][2*h+0]*s0 + h0, 0.0f);
                float v1 = fmaxf(acc[tm][tn][2*h+1]*s1 + h1, 0.0f);
                *(float2*)(out + (size_t)row*DIM + oc) = make_float2(v0, v1);
            }
        }
    }
}

// ---------------- window attention, cap=25: one warp per window, single pass ----------------
__global__ void attn25_kernel(const float* __restrict__ QK, const float* __restrict__ V,
                              float* __restrict__ O)
{
    __shared__ float Ks[4][CAP0*16], Vs[4][CAP0*16];
    int h = blockIdx.y;
    int warp = threadIdx.x >> 5, lane = threadIdx.x & 31;
    int w = blockIdx.x*4 + warp;
    int base = w * CAP0;
    for (int idx = lane; idx < CAP0*16; idx += 32) {
        int j = idx >> 4, d = idx & 15;
        Ks[warp][idx] = QK[(size_t)(base+j)*256 + 128 + h*16 + d];
        Vs[warp][idx] = V [(size_t)(base+j)*128 + h*16 + d];
    }
    __syncwarp();
    if (lane >= CAP0) return;
    float q[16];
    #pragma unroll
    for (int d = 0; d < 16; d++) q[d] = QK[(size_t)(base+lane)*256 + h*16 + d] * 0.25f;
    float sc[CAP0], mx = -1e30f;
    #pragma unroll
    for (int j = 0; j < CAP0; j++) {
        float s = 0.f;
        #pragma unroll
        for (int d = 0; d < 16; d++) s = fmaf(q[d], Ks[warp][j*16+d], s);
        sc[j] = s;
        mx = fmaxf(mx, s);
    }
    float sum = 0.f;
    #pragma unroll
    for (int j = 0; j < CAP0; j++) { sc[j] = __expf(sc[j] - mx); sum += sc[j]; }
    float inv = 1.0f / sum;
    float o[16];
    #pragma unroll
    for (int d = 0; d < 16; d++) o[d] = 0.f;
    #pragma unroll
    for (int j = 0; j < CAP0; j++)
        #pragma unroll
        for (int d = 0; d < 16; d++) o[d] = fmaf(sc[j], Vs[warp][j*16+d], o[d]);
    #pragma unroll
    for (int d = 0; d < 16; d++) O[(size_t)(base+lane)*128 + h*16 + d] = o[d] * inv;
}

// ---------------- window attention, cap=100: 128-thread block, 2-pass ----------------
__global__ void attn100_kernel(const float* __restrict__ QK, const float* __restrict__ V,
                               float* __restrict__ O)
{
    __shared__ float Ks[CAP1*16], Vs[CAP1*16];
    int w = blockIdx.x, h = blockIdx.y;
    int base = w * CAP1;
    for (int idx = threadIdx.x; idx < CAP1*16; idx += 128) {
        int j = idx >> 4, d = idx & 15;
        Ks[idx] = QK[(size_t)(base+j)*256 + 128 + h*16 + d];
        Vs[idx] = V [(size_t)(base+j)*128 + h*16 + d];
    }
    __syncthreads();
    int t = threadIdx.x;
    if (t >= CAP1) return;
    float q[16];
    #pragma unroll
    for (int d = 0; d < 16; d++) q[d] = QK[(size_t)(base+t)*256 + h*16 + d] * 0.25f;
    float mx = -1e30f, s = 0.0f;
    for (int j = 0; j < CAP1; j++) {
        float sc = 0.f;
        #pragma unroll
        for (int d = 0; d < 16; d++) sc = fmaf(q[d], Ks[j*16+d], sc);
        float m2 = fmaxf(mx, sc);
        s = s * __expf(mx - m2) + __expf(sc - m2);
        mx = m2;
    }
    float inv = 1.0f / s;
    float o[16];
    #pragma unroll
    for (int d = 0; d < 16; d++) o[d] = 0.f;
    for (int j = 0; j < CAP1; j++) {
        float sc = 0.f;
        #pragma unroll
        for (int d = 0; d < 16; d++) sc = fmaf(q[d], Ks[j*16+d], sc);
        float p = __expf(sc - mx);
        #pragma unroll
        for (int d = 0; d < 16; d++) o[d] = fmaf(p, Vs[j*16+d], o[d]);
    }
    #pragma unroll
    for (int d = 0; d < 16; d++) O[(size_t)(base+t)*128 + h*16 + d] = o[d] * inv;
}

// ---------------- residual + LayerNorm ----------------
__global__ void add_ln_kernel(const float* x, const float* r,
                              const float* __restrict__ g, const float* __restrict__ b,
                              float* out, int n)
{
    int row = blockIdx.x * blockDim.y + threadIdx.y;
    if (row >= n) return;
    int lane = threadIdx.x;
    float4 xv = ((const float4*)(x + (size_t)row*DIM))[lane];
    if (r) {
        float4 rv = ((const float4*)(r + (size_t)row*DIM))[lane];
        xv.x += rv.x; xv.y += rv.y; xv.z += rv.z; xv.w += rv.w;
    }
    float sum = xv.x + xv.y + xv.z + xv.w;
    float sq  = xv.x*xv.x + xv.y*xv.y + xv.z*xv.z + xv.w*xv.w;
    #pragma unroll
    for (int o = 16; o; o >>= 1) {
        sum += __shfl_xor_sync(0xffffffffu, sum, o);
        sq  += __shfl_xor_sync(0xffffffffu, sq,  o);
    }
    float mu  = sum * (1.0f/128.0f);
    float var = sq  * (1.0f/128.0f) - mu*mu;
    float rstd = rsqrtf(var + 1e-5f);
    float4 gv = ((const float4*)g)[lane];
    float4 bv = ((const float4*)b)[lane];
    float4 ov;
    ov.x = (xv.x - mu)*rstd*gv.x + bv.x;
    ov.y = (xv.y - mu)*rstd*gv.y + bv.y;
    ov.z = (xv.z - mu)*rstd*gv.z + bv.z;
    ov.w = (xv.w - mu)*rstd*gv.w + bv.w;
    ((float4*)(out + (size_t)row*DIM))[lane] = ov;
}

// ---------------- BEV helpers ----------------
__global__ void zero_kernel(float4* __restrict__ p, int n4)
{
    int i = blockIdx.x*blockDim.x + threadIdx.x;
    if (i < n4) p[i] = make_float4(0.f,0.f,0.f,0.f);
}

__global__ void bev_scatter_kernel(const float* __restrict__ feat, const int* __restrict__ coors,
                                   float* __restrict__ canvas)
{
    int j = blockIdx.x, c = threadIdx.x;
    int b = coors[j*4], y = coors[j*4+2], x = coors[j*4+3];
    canvas[((size_t)((b*NYY + y)*NXX + x))*DIM + c] = feat[(size_t)j*DIM + c];
}

__global__ void wt_kernel(const float* __restrict__ cw, float* __restrict__ wt)
{
    int t = blockIdx.x*blockDim.x + threadIdx.x;
    if (t >= 2*128*9*128) return;
    int ic  = t & 127;
    int tap = (t >> 7) % 9;
    int oci = t / (128*9);
    wt[((size_t)oci*9 + tap)*128 + ic] = cw[((size_t)oci*128 + ic)*9 + tap];
}

// tiled NHWC -> NCHW transpose (coalesced both sides)
__global__ void to_nchw_kernel(const float* __restrict__ in, float* __restrict__ out)
{
    __shared__ float t[32][33];
    int p0 = blockIdx.x * 32;
    int c0 = blockIdx.y * 32;
    for (int i = threadIdx.y; i < 32; i += 8)
        t[i][threadIdx.x] = in[(size_t)(p0 + i)*DIM + c0 + threadIdx.x];
    __syncthreads();
    for (int i = threadIdx.y; i < 32; i += 8) {
        int c = c0 + i;
        int p = p0 + threadIdx.x;
        int b = p / (NYY*NXX);
        int rem = p - b*(NYY*NXX);
        out[((size_t)(b*DIM + c))*(NYY*NXX) + rem] = t[threadIdx.x][i];
    }
}

// ---------------- orchestration ----------------
extern "C" void kernel_launch(void* const* d_in, const int* in_sizes, int n_in,
                              void* d_out, int out_size)
{
    const float* vfeat = (const float*)d_in[0];
    const int*   coors = (const int*)  d_in[1];
    const float* ciw0  = (const float*)d_in[2];
    const float* ciw1  = (const float*)d_in[3];
    const int* vx[2][2] = {
        { (const int*)d_in[4],  (const int*)d_in[6]  },
        { (const int*)d_in[8],  (const int*)d_in[10] }
    };
    const float* ipw = (const float*)d_in[12];
    const float* ipb = (const float*)d_in[13];
    const float* ow_ = (const float*)d_in[14];
    const float* ob_ = (const float*)d_in[15];
    const float* l1w = (const float*)d_in[16];
    const float* l1b = (const float*)d_in[17];
    const float* l2w = (const float*)d_in[18];
    const float* l2b = (const float*)d_in[19];
    const float* g1  = (const float*)d_in[20];
    const float* b1  = (const float*)d_in[21];
    const float* g2  = (const float*)d_in[22];
    const float* b2  = (const float*)d_in[23];
    const float* cw  = (const float*)d_in[24];
    const float* bg  = (const float*)d_in[25];
    const float* bb  = (const float*)d_in[26];
    const float* bm  = (const float*)d_in[27];
    const float* bvv = (const float*)d_in[28];

    float *pos, *feat, *resid, *qkin, *qk, *vbuf, *ao, *h, *canvas, *bev, *wt;
    cudaGetSymbolAddress((void**)&pos,    g_pos);
    cudaGetSymbolAddress((void**)&feat,   g_feat);
    cudaGetSymbolAddress((void**)&resid,  g_resid);
    cudaGetSymbolAddress((void**)&qkin,   g_qkin);
    cudaGetSymbolAddress((void**)&qk,     g_qk);
    cudaGetSymbolAddress((void**)&vbuf,   g_v);
    cudaGetSymbolAddress((void**)&ao,     g_ao);
    cudaGetSymbolAddress((void**)&h,      g_h);
    cudaGetSymbolAddress((void**)&canvas, g_canvas);
    cudaGetSymbolAddress((void**)&bev,    g_bev);
    cudaGetSymbolAddress((void**)&wt,     g_wt);

    // opt-in to >48KB dynamic smem for each MMA kernel instantiation
    cudaFuncSetAttribute(gemm_tc<0,0,0>, cudaFuncAttributeMaxDynamicSharedMemorySize, SMEMB);
    cudaFuncSetAttribute(gemm_tc<0,2,0>, cudaFuncAttributeMaxDynamicSharedMemorySize, SMEMB);
    cudaFuncSetAttribute(gemm_tc<0,0,1>, cudaFuncAttributeMaxDynamicSharedMemorySize, SMEMB);
    cudaFuncSetAttribute(gemm_tc<1,0,0>, cudaFuncAttributeMaxDynamicSharedMemorySize, SMEMB);
    cudaFuncSetAttribute(conv_tc,        cudaFuncAttributeMaxDynamicSharedMemorySize, SMEMB);

    pos_kernel<<<dim3(NVOX, 2), 128>>>(ciw0, ciw1, pos);
    wt_kernel<<<(2*128*9*128 + 255)/256, 256>>>(cw, wt);

    const float* cur = vfeat;
    for (int li = 0; li < NLAYER; li++) {
        int s = li & 1;
        const float* posS = pos + (size_t)s*NVOX*DIM;
        for (int lvl = 0; lvl < 2; lvl++) {
            const int* vxp = vx[s][lvl];
            int ln  = lvl ? LN1 : LN0;
            int my  = (ln + 127) / 128;

            gatherQ_kernel<<<ln, 128>>>(cur, posS, vxp, qkin);
            // QK fused GEMM (N=256)
            gemm_tc<0,0,0><<<dim3(2, my), 256, SMEMB>>>(qkin, ipw + (size_t)li*384*128,
                                                        ipb + (size_t)li*384, qk,
                                                        nullptr, nullptr, ln, 256, 128);
            // V GEMM with row gather
            gemm_tc<0,2,0><<<dim3(1, my), 256, SMEMB>>>(cur, ipw + (size_t)li*384*128 + 256*128,
                                                        ipb + (size_t)li*384 + 256, vbuf,
                                                        vxp, nullptr, ln, 128, 128);
            if (lvl == 0) attn25_kernel <<<dim3(NW0/4, 8), 128>>>(qk, vbuf, ao);
            else          attn100_kernel<<<dim3(NW1,   8), 128>>>(qk, vbuf, ao);
            // out-proj with residual-add + scatter epilogue
            gemm_tc<0,0,1><<<dim3(1, my), 256, SMEMB>>>(ao, ow_ + (size_t)li*128*128,
                                                        ob_ + (size_t)li*128, resid,
                                                        vxp, cur, ln, 128, 128);
        }
        add_ln_kernel<<<(NVOX + 7)/8, dim3(32, 8)>>>(resid, nullptr,
                                                     g1 + (size_t)li*128, b1 + (size_t)li*128, feat, NVOX);
        gemm_tc<1,0,0><<<dim3(2, (NVOX + 127)/128), 256, SMEMB>>>(feat, l1w + (size_t)li*256*128,
                                                                  l1b + (size_t)li*256, h,
                                                                  nullptr, nullptr, NVOX, 256, 128);
        gemm_tc<0,0,0><<<dim3(1, (NVOX + 127)/128), 256, SMEMB>>>(h, l2w + (size_t)li*128*256,
                                                                  l2b + (size_t)li*128, resid,
                                                                  nullptr, nullptr, NVOX, 128, 256);
        add_ln_kernel<<<(NVOX + 7)/8, dim3(32, 8)>>>(feat, resid,
                                                     g2 + (size_t)li*128, b2 + (size_t)li*128, feat, NVOX);
        cur = feat;
    }

    int n4 = (int)((size_t)NPIX*DIM/4);
    zero_kernel<<<(n4 + 255)/256, 256>>>((float4*)canvas, n4);
    bev_scatter_kernel<<<NVOX, 128>>>(feat, coors, canvas);
    conv_tc<<<NPIX/128, 256, SMEMB>>>(canvas, wt,            bg,       bb,       bm,       bvv,       bev);
    conv_tc<<<NPIX/128, 256, SMEMB>>>(bev,    wt + 128*1152, bg + 128, bb + 128, bm + 128, bvv + 128, canvas);
    to_nchw_kernel<<<dim3(NPIX/32, 4), dim3(32, 8)>>>(canvas, (float*)d_out);
}